// round 9
// baseline (speedup 1.0000x reference)
#include <cuda_runtime.h>
#include <math.h>

// Problem-shape capacities (actual sizes read from in_sizes at runtime).
#define HDIM   128
#define NMAX   100096
#define EMAX   221184
#define NBMAX  512     // max scan blocks: ceil(NMAX/256) = 392 <= 512

// ---------------- scratch (device globals; allocation is forbidden) --------
__device__ float g_hx[(size_t)NMAX * 256];   // x @ [W1 | Wv1]
__device__ float g_h1[(size_t)NMAX * 256];   // relu(conv1) for both branches
__device__ float g_dinv[2][NMAX];
__device__ int   g_deg [2][NMAX];
__device__ int   g_off [2][NMAX];
__device__ int   g_fill[2][NMAX];
__device__ int   g_csr [2][EMAX];
__device__ float g_h2  [2][NMAX];
__device__ int   g_bsum[2][NBMAX];
__device__ int   g_bpre[2][NBMAX];

// ---------------- setup kernels --------------------------------------------
__global__ void k_zero(int n, float* y, int g) {
    int i = blockIdx.x * blockDim.x + threadIdx.x;
    if (i < n) {
        g_deg[0][i] = 0; g_deg[1][i] = 0;
        g_fill[0][i] = 0; g_fill[1][i] = 0;
    }
    if (i < g) y[i] = 0.0f;
}

__global__ void k_deg(const int* __restrict__ ei, const int* __restrict__ vei, int E) {
    int e = blockIdx.x * blockDim.x + threadIdx.x;
    if (e >= E) return;
    atomicAdd(&g_deg[0][ei [E + e]], 1);
    atomicAdd(&g_deg[1][vei[E + e]], 1);
}

__global__ void k_dinv(int n) {
    int i = blockIdx.x * blockDim.x + threadIdx.x;
    if (i >= n) return;
    g_dinv[0][i] = rsqrtf((float)g_deg[0][i] + 1.0f);
    g_dinv[1][i] = rsqrtf((float)g_deg[1][i] + 1.0f);
}

// ---------------- 3-kernel exclusive scan of g_deg -> g_off ----------------
__global__ void k_scan1(int n) {
    int b = blockIdx.y;
    int tid = threadIdx.x;
    int i = blockIdx.x * 256 + tid;
    int v = (i < n) ? g_deg[b][i] : 0;
    __shared__ int s[256];
    s[tid] = v; __syncthreads();
    #pragma unroll
    for (int d = 1; d < 256; d <<= 1) {
        int t = (tid >= d) ? s[tid - d] : 0;
        __syncthreads();
        s[tid] += t;
        __syncthreads();
    }
    if (i < n) g_off[b][i] = s[tid] - v;       // exclusive within block
    if (tid == 255) g_bsum[b][blockIdx.x] = s[255];
}

__global__ void k_scan2(int nb) {
    int b = blockIdx.y;
    int tid = threadIdx.x;                     // 512 threads
    int v = (tid < nb) ? g_bsum[b][tid] : 0;
    __shared__ int s[512];
    s[tid] = v; __syncthreads();
    #pragma unroll
    for (int d = 1; d < 512; d <<= 1) {
        int t = (tid >= d) ? s[tid - d] : 0;
        __syncthreads();
        s[tid] += t;
        __syncthreads();
    }
    if (tid < nb) g_bpre[b][tid] = s[tid] - v; // exclusive block prefix
}

__global__ void k_scan3(int n) {
    int b = blockIdx.y;
    int i = blockIdx.x * 256 + threadIdx.x;
    if (i < n) g_off[b][i] += g_bpre[b][blockIdx.x];
}

__global__ void k_fill(const int* __restrict__ ei, const int* __restrict__ vei, int E) {
    int e = blockIdx.x * blockDim.x + threadIdx.x;
    if (e >= E) return;
    {
        int s = ei[e], d = ei[E + e];
        int p = g_off[0][d] + atomicAdd(&g_fill[0][d], 1);
        g_csr[0][p] = s;
    }
    {
        int s = vei[e], d = vei[E + e];
        int p = g_off[1][d] + atomicAdd(&g_fill[1][d], 1);
        g_csr[1][p] = s;
    }
}

// ---------------- x = embed[tok] + pe @ Wt + bt  (written to d_out) --------
__global__ void k_x(const int* __restrict__ tok, const float* __restrict__ pe,
                    const float* __restrict__ emb, const float* __restrict__ Wt,
                    const float* __restrict__ bt, float* __restrict__ xout, int n) {
    int idx = blockIdx.x * blockDim.x + threadIdx.x;
    if (idx >= n * HDIM) return;
    int node = idx >> 7;
    int h = idx & 127;
    int t = tok[node];
    const float* pn = pe + (size_t)node * 5;
    float acc = emb[t * HDIM + h] + bt[h];
    #pragma unroll
    for (int p = 0; p < 5; ++p) acc = fmaf(pn[p], Wt[p * HDIM + h], acc);
    xout[idx] = acc;
}

// ---------------- SGEMM: g_hx[N,256] = x[N,128] @ [W1 | Wv1] ----------------
// 128x128 tile per block, BK=8, 256 threads, 8x8 per thread.
__global__ __launch_bounds__(256)
void k_gemm(const float* __restrict__ A, const float* __restrict__ W1,
            const float* __restrict__ Wv1, int M) {
    const float* B = blockIdx.y ? Wv1 : W1;    // [128,128] row-major (K x N)
    int row0 = blockIdx.x * 128;
    __shared__ float As[8][128];
    __shared__ float Bs[8][128];
    int tid = threadIdx.x;
    int tx = tid & 15, ty = tid >> 4;          // 16x16 thread grid
    float acc[8][8];
    #pragma unroll
    for (int i = 0; i < 8; ++i)
        #pragma unroll
        for (int j = 0; j < 8; ++j) acc[i][j] = 0.0f;

    int arow = tid >> 1;
    int acol = (tid & 1) * 4;
    int brow = tid >> 5;
    int bcol = (tid & 31) * 4;

    for (int k0 = 0; k0 < 128; k0 += 8) {
        float4 av = make_float4(0.f, 0.f, 0.f, 0.f);
        int gr = row0 + arow;
        if (gr < M) av = *(const float4*)(A + (size_t)gr * 128 + k0 + acol);
        As[acol + 0][arow] = av.x;
        As[acol + 1][arow] = av.y;
        As[acol + 2][arow] = av.z;
        As[acol + 3][arow] = av.w;
        *(float4*)&Bs[brow][bcol] = *(const float4*)(B + (k0 + brow) * 128 + bcol);
        __syncthreads();
        #pragma unroll
        for (int k = 0; k < 8; ++k) {
            float a[8], b[8];
            *(float4*)&a[0] = *(float4*)&As[k][ty * 8];
            *(float4*)&a[4] = *(float4*)&As[k][ty * 8 + 4];
            *(float4*)&b[0] = *(float4*)&Bs[k][tx * 8];
            *(float4*)&b[4] = *(float4*)&Bs[k][tx * 8 + 4];
            #pragma unroll
            for (int i = 0; i < 8; ++i)
                #pragma unroll
                for (int j = 0; j < 8; ++j)
                    acc[i][j] = fmaf(a[i], b[j], acc[i][j]);
        }
        __syncthreads();
    }
    int colbase = blockIdx.y * 128 + tx * 8;
    #pragma unroll
    for (int i = 0; i < 8; ++i) {
        int r = row0 + ty * 8 + i;
        if (r < M) {
            float* dst = &g_hx[(size_t)r * 256 + colbase];
            *(float4*)(dst)     = make_float4(acc[i][0], acc[i][1], acc[i][2], acc[i][3]);
            *(float4*)(dst + 4) = make_float4(acc[i][4], acc[i][5], acc[i][6], acc[i][7]);
        }
    }
}

// -------- conv1 aggregation (gather over CSR) + bias + relu -> g_h1 --------
// One warp per (node, branch); 128 dims -> float4 per lane.
__global__ void k_agg1(const float* __restrict__ b1, const float* __restrict__ bv1, int n) {
    int warp = (blockIdx.x * blockDim.x + threadIdx.x) >> 5;
    int lane = threadIdx.x & 31;
    if (warp >= 2 * n) return;
    int br = (warp >= n) ? 1 : 0;
    int node = br ? (warp - n) : warp;
    int start = g_off[br][node];
    int cnt = g_deg[br][node];
    int half = br * 128;
    float4 acc = make_float4(0.f, 0.f, 0.f, 0.f);
    for (int e = 0; e < cnt; ++e) {
        int s = g_csr[br][start + e];
        float w = g_dinv[br][s];
        float4 v = *(const float4*)&g_hx[(size_t)s * 256 + half + lane * 4];
        acc.x = fmaf(v.x, w, acc.x);
        acc.y = fmaf(v.y, w, acc.y);
        acc.z = fmaf(v.z, w, acc.z);
        acc.w = fmaf(v.w, w, acc.w);
    }
    float di = g_dinv[br][node];
    float d2 = di * di;
    float4 sv = *(const float4*)&g_hx[(size_t)node * 256 + half + lane * 4];
    const float* bias = br ? bv1 : b1;
    float4 bb = *(const float4*)&bias[lane * 4];
    float4 r;
    r.x = fmaxf(fmaf(acc.x, di, fmaf(sv.x, d2, bb.x)), 0.f);
    r.y = fmaxf(fmaf(acc.y, di, fmaf(sv.y, d2, bb.y)), 0.f);
    r.z = fmaxf(fmaf(acc.z, di, fmaf(sv.z, d2, bb.z)), 0.f);
    r.w = fmaxf(fmaf(acc.w, di, fmaf(sv.w, d2, bb.w)), 0.f);
    *(float4*)&g_h1[(size_t)node * 256 + half + lane * 4] = r;
}

// -------- layer-2 projection h2 = h1 @ W2 (scalar per node per branch) -----
__global__ void k_h2(const float* __restrict__ W2, const float* __restrict__ Wv2, int n) {
    int warp = (blockIdx.x * blockDim.x + threadIdx.x) >> 5;
    int lane = threadIdx.x & 31;
    if (warp >= n) return;
    float4 a  = *(const float4*)&g_h1[(size_t)warp * 256 + lane * 4];
    float4 w  = *(const float4*)&W2[lane * 4];
    float4 av = *(const float4*)&g_h1[(size_t)warp * 256 + 128 + lane * 4];
    float4 wv = *(const float4*)&Wv2[lane * 4];
    float s1 = a.x * w.x + a.y * w.y + a.z * w.z + a.w * w.w;
    float sv = av.x * wv.x + av.y * wv.y + av.z * wv.z + av.w * wv.w;
    #pragma unroll
    for (int o = 16; o > 0; o >>= 1) {
        s1 += __shfl_down_sync(0xFFFFFFFFu, s1, o);
        sv += __shfl_down_sync(0xFFFFFFFFu, sv, o);
    }
    if (lane == 0) { g_h2[0][warp] = s1; g_h2[1][warp] = sv; }
}

// -------- conv2 aggregation (scalar) + sum branches + graph pooling --------
__global__ void k_out(const int* __restrict__ batch, const float* __restrict__ b2,
                      const float* __restrict__ bv2, float* __restrict__ y, int n) {
    int node = blockIdx.x * blockDim.x + threadIdx.x;
    if (node >= n) return;
    float acc = b2[0] + bv2[0];
    #pragma unroll
    for (int br = 0; br < 2; ++br) {
        int start = g_off[br][node];
        int cnt = g_deg[br][node];
        float t = 0.f;
        for (int e = 0; e < cnt; ++e) {
            int s = g_csr[br][start + e];
            t = fmaf(g_h2[br][s], g_dinv[br][s], t);
        }
        float di = g_dinv[br][node];
        acc += di * t + g_h2[br][node] * di * di;
    }
    atomicAdd(&y[batch[node]], acc);
}

// ---------------------------------------------------------------------------
extern "C" void kernel_launch(void* const* d_in, const int* in_sizes, int n_in,
                              void* d_out, int out_size) {
    const int*   tok  = (const int*)  d_in[0];
    const float* pe   = (const float*)d_in[1];
    const int*   ei   = (const int*)  d_in[2];
    const int*   vei  = (const int*)  d_in[3];
    const int*   batch= (const int*)  d_in[4];
    const float* emb  = (const float*)d_in[5];
    const float* Wt   = (const float*)d_in[6];
    const float* bt   = (const float*)d_in[7];
    const float* W1   = (const float*)d_in[8];
    const float* b1   = (const float*)d_in[9];
    const float* W2   = (const float*)d_in[10];
    const float* b2   = (const float*)d_in[11];
    const float* Wv1  = (const float*)d_in[12];
    const float* bv1  = (const float*)d_in[13];
    const float* Wv2  = (const float*)d_in[14];
    const float* bv2  = (const float*)d_in[15];

    int N = in_sizes[0];              // 100000
    int E = in_sizes[2] / 2;          // 220000
    int G = out_size - N * HDIM;      // 4096 (output = [y | x])
    float* y = (float*)d_out;
    float* xout = y + G;

    int nz = (N > G) ? N : G;
    k_zero<<<(nz + 255) / 256, 256>>>(N, y, G);
    k_deg<<<(E + 255) / 256, 256>>>(ei, vei, E);
    k_dinv<<<(N + 255) / 256, 256>>>(N);

    int NB = (N + 255) / 256;
    k_scan1<<<dim3(NB, 2), 256>>>(N);
    k_scan2<<<dim3(1, 2), 512>>>(NB);
    k_scan3<<<dim3(NB, 2), 256>>>(N);
    k_fill<<<(E + 255) / 256, 256>>>(ei, vei, E);

    k_x<<<(N * HDIM + 255) / 256, 256>>>(tok, pe, emb, Wt, bt, xout, N);
    k_gemm<<<dim3((N + 127) / 128, 2), 256>>>(xout, W1, Wv1, N);
    k_agg1<<<(2 * N * 32 + 255) / 256, 256>>>(b1, bv1, N);
    k_h2<<<(N * 32 + 255) / 256, 256>>>(W2, Wv2, N);
    k_out<<<(N + 255) / 256, 256>>>(batch, b2, bv2, y, N);
}

// round 10
// speedup vs baseline: 1.0021x; 1.0021x over previous
#include <cuda_runtime.h>
#include <math.h>

// Problem-shape capacities (actual sizes read from in_sizes at runtime).
#define HDIM   128
#define NMAX   100096
#define EMAX   221184
#define NBMAX  512     // max scan blocks: ceil(NMAX/256) = 392 <= 512

// ---------------- scratch (device globals; allocation is forbidden) --------
__device__ float g_hx[(size_t)NMAX * 256];   // x @ [W1 | Wv1]
__device__ float g_h1[(size_t)NMAX * 256];   // relu(conv1) for both branches
__device__ float g_dinv[2][NMAX];
__device__ int   g_deg [2][NMAX];
__device__ int   g_off [2][NMAX];
__device__ int   g_fill[2][NMAX];
__device__ int   g_csr [2][EMAX];
__device__ float g_h2  [2][NMAX];
__device__ int   g_bsum[2][NBMAX];
__device__ int   g_bpre[2][NBMAX];

// ---------------- setup kernels --------------------------------------------
__global__ void k_zero(int n, float* y, int g) {
    int i = blockIdx.x * blockDim.x + threadIdx.x;
    if (i < n) {
        g_deg[0][i] = 0; g_deg[1][i] = 0;
        g_fill[0][i] = 0; g_fill[1][i] = 0;
    }
    if (i < g) y[i] = 0.0f;
}

__global__ void k_deg(const int* __restrict__ ei, const int* __restrict__ vei, int E) {
    int e = blockIdx.x * blockDim.x + threadIdx.x;
    if (e >= E) return;
    atomicAdd(&g_deg[0][ei [E + e]], 1);
    atomicAdd(&g_deg[1][vei[E + e]], 1);
}

__global__ void k_dinv(int n) {
    int i = blockIdx.x * blockDim.x + threadIdx.x;
    if (i >= n) return;
    g_dinv[0][i] = rsqrtf((float)g_deg[0][i] + 1.0f);
    g_dinv[1][i] = rsqrtf((float)g_deg[1][i] + 1.0f);
}

// ---------------- 3-kernel exclusive scan of g_deg -> g_off ----------------
__global__ void k_scan1(int n) {
    int b = blockIdx.y;
    int tid = threadIdx.x;
    int i = blockIdx.x * 256 + tid;
    int v = (i < n) ? g_deg[b][i] : 0;
    __shared__ int s[256];
    s[tid] = v; __syncthreads();
    #pragma unroll
    for (int d = 1; d < 256; d <<= 1) {
        int t = (tid >= d) ? s[tid - d] : 0;
        __syncthreads();
        s[tid] += t;
        __syncthreads();
    }
    if (i < n) g_off[b][i] = s[tid] - v;       // exclusive within block
    if (tid == 255) g_bsum[b][blockIdx.x] = s[255];
}

__global__ void k_scan2(int nb) {
    int b = blockIdx.y;
    int tid = threadIdx.x;                     // 512 threads
    int v = (tid < nb) ? g_bsum[b][tid] : 0;
    __shared__ int s[512];
    s[tid] = v; __syncthreads();
    #pragma unroll
    for (int d = 1; d < 512; d <<= 1) {
        int t = (tid >= d) ? s[tid - d] : 0;
        __syncthreads();
        s[tid] += t;
        __syncthreads();
    }
    if (tid < nb) g_bpre[b][tid] = s[tid] - v; // exclusive block prefix
}

__global__ void k_scan3(int n) {
    int b = blockIdx.y;
    int i = blockIdx.x * 256 + threadIdx.x;
    if (i < n) g_off[b][i] += g_bpre[b][blockIdx.x];
}

__global__ void k_fill(const int* __restrict__ ei, const int* __restrict__ vei, int E) {
    int e = blockIdx.x * blockDim.x + threadIdx.x;
    if (e >= E) return;
    {
        int s = ei[e], d = ei[E + e];
        int p = g_off[0][d] + atomicAdd(&g_fill[0][d], 1);
        g_csr[0][p] = s;
    }
    {
        int s = vei[e], d = vei[E + e];
        int p = g_off[1][d] + atomicAdd(&g_fill[1][d], 1);
        g_csr[1][p] = s;
    }
}

// ---------------- x = embed[tok] + pe @ Wt + bt  (written to d_out) --------
__global__ void k_x(const int* __restrict__ tok, const float* __restrict__ pe,
                    const float* __restrict__ emb, const float* __restrict__ Wt,
                    const float* __restrict__ bt, float* __restrict__ xout, int n) {
    int idx = blockIdx.x * blockDim.x + threadIdx.x;
    if (idx >= n * HDIM) return;
    int node = idx >> 7;
    int h = idx & 127;
    int t = tok[node];
    const float* pn = pe + (size_t)node * 5;
    float acc = emb[t * HDIM + h] + bt[h];
    #pragma unroll
    for (int p = 0; p < 5; ++p) acc = fmaf(pn[p], Wt[p * HDIM + h], acc);
    xout[idx] = acc;
}

// ---------------- SGEMM: g_hx[N,256] = x[N,128] @ [W1 | Wv1] ----------------
// 128x128 tile per block, BK=8, 256 threads, 8x8 per thread.
__global__ __launch_bounds__(256)
void k_gemm(const float* __restrict__ A, const float* __restrict__ W1,
            const float* __restrict__ Wv1, int M) {
    const float* B = blockIdx.y ? Wv1 : W1;    // [128,128] row-major (K x N)
    int row0 = blockIdx.x * 128;
    __shared__ float As[8][128];
    __shared__ float Bs[8][128];
    int tid = threadIdx.x;
    int tx = tid & 15, ty = tid >> 4;          // 16x16 thread grid
    float acc[8][8];
    #pragma unroll
    for (int i = 0; i < 8; ++i)
        #pragma unroll
        for (int j = 0; j < 8; ++j) acc[i][j] = 0.0f;

    int arow = tid >> 1;
    int acol = (tid & 1) * 4;
    int brow = tid >> 5;
    int bcol = (tid & 31) * 4;

    for (int k0 = 0; k0 < 128; k0 += 8) {
        float4 av = make_float4(0.f, 0.f, 0.f, 0.f);
        int gr = row0 + arow;
        if (gr < M) av = *(const float4*)(A + (size_t)gr * 128 + k0 + acol);
        As[acol + 0][arow] = av.x;
        As[acol + 1][arow] = av.y;
        As[acol + 2][arow] = av.z;
        As[acol + 3][arow] = av.w;
        *(float4*)&Bs[brow][bcol] = *(const float4*)(B + (k0 + brow) * 128 + bcol);
        __syncthreads();
        #pragma unroll
        for (int k = 0; k < 8; ++k) {
            float a[8], b[8];
            *(float4*)&a[0] = *(float4*)&As[k][ty * 8];
            *(float4*)&a[4] = *(float4*)&As[k][ty * 8 + 4];
            *(float4*)&b[0] = *(float4*)&Bs[k][tx * 8];
            *(float4*)&b[4] = *(float4*)&Bs[k][tx * 8 + 4];
            #pragma unroll
            for (int i = 0; i < 8; ++i)
                #pragma unroll
                for (int j = 0; j < 8; ++j)
                    acc[i][j] = fmaf(a[i], b[j], acc[i][j]);
        }
        __syncthreads();
    }
    int colbase = blockIdx.y * 128 + tx * 8;
    #pragma unroll
    for (int i = 0; i < 8; ++i) {
        int r = row0 + ty * 8 + i;
        if (r < M) {
            float* dst = &g_hx[(size_t)r * 256 + colbase];
            *(float4*)(dst)     = make_float4(acc[i][0], acc[i][1], acc[i][2], acc[i][3]);
            *(float4*)(dst + 4) = make_float4(acc[i][4], acc[i][5], acc[i][6], acc[i][7]);
        }
    }
}

// -------- conv1 aggregation (gather over CSR) + bias + relu -> g_h1 --------
// One warp per (node, branch); 128 dims -> float4 per lane.
__global__ void k_agg1(const float* __restrict__ b1, const float* __restrict__ bv1, int n) {
    int warp = (blockIdx.x * blockDim.x + threadIdx.x) >> 5;
    int lane = threadIdx.x & 31;
    if (warp >= 2 * n) return;
    int br = (warp >= n) ? 1 : 0;
    int node = br ? (warp - n) : warp;
    int start = g_off[br][node];
    int cnt = g_deg[br][node];
    int half = br * 128;
    float4 acc = make_float4(0.f, 0.f, 0.f, 0.f);
    for (int e = 0; e < cnt; ++e) {
        int s = g_csr[br][start + e];
        float w = g_dinv[br][s];
        float4 v = *(const float4*)&g_hx[(size_t)s * 256 + half + lane * 4];
        acc.x = fmaf(v.x, w, acc.x);
        acc.y = fmaf(v.y, w, acc.y);
        acc.z = fmaf(v.z, w, acc.z);
        acc.w = fmaf(v.w, w, acc.w);
    }
    float di = g_dinv[br][node];
    float d2 = di * di;
    float4 sv = *(const float4*)&g_hx[(size_t)node * 256 + half + lane * 4];
    const float* bias = br ? bv1 : b1;
    float4 bb = *(const float4*)&bias[lane * 4];
    float4 r;
    r.x = fmaxf(fmaf(acc.x, di, fmaf(sv.x, d2, bb.x)), 0.f);
    r.y = fmaxf(fmaf(acc.y, di, fmaf(sv.y, d2, bb.y)), 0.f);
    r.z = fmaxf(fmaf(acc.z, di, fmaf(sv.z, d2, bb.z)), 0.f);
    r.w = fmaxf(fmaf(acc.w, di, fmaf(sv.w, d2, bb.w)), 0.f);
    *(float4*)&g_h1[(size_t)node * 256 + half + lane * 4] = r;
}

// -------- layer-2 projection h2 = h1 @ W2 (scalar per node per branch) -----
__global__ void k_h2(const float* __restrict__ W2, const float* __restrict__ Wv2, int n) {
    int warp = (blockIdx.x * blockDim.x + threadIdx.x) >> 5;
    int lane = threadIdx.x & 31;
    if (warp >= n) return;
    float4 a  = *(const float4*)&g_h1[(size_t)warp * 256 + lane * 4];
    float4 w  = *(const float4*)&W2[lane * 4];
    float4 av = *(const float4*)&g_h1[(size_t)warp * 256 + 128 + lane * 4];
    float4 wv = *(const float4*)&Wv2[lane * 4];
    float s1 = a.x * w.x + a.y * w.y + a.z * w.z + a.w * w.w;
    float sv = av.x * wv.x + av.y * wv.y + av.z * wv.z + av.w * wv.w;
    #pragma unroll
    for (int o = 16; o > 0; o >>= 1) {
        s1 += __shfl_down_sync(0xFFFFFFFFu, s1, o);
        sv += __shfl_down_sync(0xFFFFFFFFu, sv, o);
    }
    if (lane == 0) { g_h2[0][warp] = s1; g_h2[1][warp] = sv; }
}

// -------- conv2 aggregation (scalar) + sum branches + graph pooling --------
__global__ void k_out(const int* __restrict__ batch, const float* __restrict__ b2,
                      const float* __restrict__ bv2, float* __restrict__ y, int n) {
    int node = blockIdx.x * blockDim.x + threadIdx.x;
    if (node >= n) return;
    float acc = b2[0] + bv2[0];
    #pragma unroll
    for (int br = 0; br < 2; ++br) {
        int start = g_off[br][node];
        int cnt = g_deg[br][node];
        float t = 0.f;
        for (int e = 0; e < cnt; ++e) {
            int s = g_csr[br][start + e];
            t = fmaf(g_h2[br][s], g_dinv[br][s], t);
        }
        float di = g_dinv[br][node];
        acc += di * t + g_h2[br][node] * di * di;
    }
    atomicAdd(&y[batch[node]], acc);
}

// ---------------------------------------------------------------------------
extern "C" void kernel_launch(void* const* d_in, const int* in_sizes, int n_in,
                              void* d_out, int out_size) {
    const int*   tok  = (const int*)  d_in[0];
    const float* pe   = (const float*)d_in[1];
    const int*   ei   = (const int*)  d_in[2];
    const int*   vei  = (const int*)  d_in[3];
    const int*   batch= (const int*)  d_in[4];
    const float* emb  = (const float*)d_in[5];
    const float* Wt   = (const float*)d_in[6];
    const float* bt   = (const float*)d_in[7];
    const float* W1   = (const float*)d_in[8];
    const float* b1   = (const float*)d_in[9];
    const float* W2   = (const float*)d_in[10];
    const float* b2   = (const float*)d_in[11];
    const float* Wv1  = (const float*)d_in[12];
    const float* bv1  = (const float*)d_in[13];
    const float* Wv2  = (const float*)d_in[14];
    const float* bv2  = (const float*)d_in[15];

    int N = in_sizes[0];              // 100000
    int E = in_sizes[2] / 2;          // 220000
    int G = out_size - N * HDIM;      // 4096 (output = [y | x])
    float* y = (float*)d_out;
    float* xout = y + G;

    int nz = (N > G) ? N : G;
    k_zero<<<(nz + 255) / 256, 256>>>(N, y, G);
    k_deg<<<(E + 255) / 256, 256>>>(ei, vei, E);
    k_dinv<<<(N + 255) / 256, 256>>>(N);

    int NB = (N + 255) / 256;
    k_scan1<<<dim3(NB, 2), 256>>>(N);
    k_scan2<<<dim3(1, 2), 512>>>(NB);
    k_scan3<<<dim3(NB, 2), 256>>>(N);
    k_fill<<<(E + 255) / 256, 256>>>(ei, vei, E);

    k_x<<<(N * HDIM + 255) / 256, 256>>>(tok, pe, emb, Wt, bt, xout, N);
    k_gemm<<<dim3((N + 127) / 128, 2), 256>>>(xout, W1, Wv1, N);
    k_agg1<<<(2 * N * 32 + 255) / 256, 256>>>(b1, bv1, N);
    k_h2<<<(N * 32 + 255) / 256, 256>>>(W2, Wv2, N);
    k_out<<<(N + 255) / 256, 256>>>(batch, b2, bv2, y, N);
}

// round 11
// speedup vs baseline: 1.0935x; 1.0912x over previous
#include <cuda_runtime.h>
#include <math.h>
#include <stdint.h>

// Problem-shape capacities (actual sizes read from in_sizes at runtime).
#define HDIM   128
#define NMAX   100096
#define EMAX   221184
#define NBMAX  512     // max scan blocks: ceil(NMAX/256) = 392 <= 512

// ---------------- scratch (device globals; allocation is forbidden) --------
__device__ float g_hx[(size_t)NMAX * 256];   // x @ [W1 | Wv1]
__device__ float g_dinv[2][NMAX];
__device__ int   g_deg [2][NMAX];
__device__ int   g_off [2][NMAX];
__device__ int   g_fill[2][NMAX];
__device__ int   g_csr [2][EMAX];
__device__ float g_h2  [2][NMAX];
__device__ int   g_bsum[2][NBMAX];
__device__ int   g_bpre[2][NBMAX];

// ---------------- setup kernels --------------------------------------------
__global__ void k_zero(int n, float* y, int g) {
    int i = blockIdx.x * blockDim.x + threadIdx.x;
    if (i < n) {
        g_deg[0][i] = 0; g_deg[1][i] = 0;
        g_fill[0][i] = 0; g_fill[1][i] = 0;
    }
    if (i < g) y[i] = 0.0f;
}

__global__ void k_deg(const int* __restrict__ ei, const int* __restrict__ vei, int E) {
    int e = blockIdx.x * blockDim.x + threadIdx.x;
    if (e >= E) return;
    atomicAdd(&g_deg[0][ei [E + e]], 1);
    atomicAdd(&g_deg[1][vei[E + e]], 1);
}

__global__ void k_dinv(int n) {
    int i = blockIdx.x * blockDim.x + threadIdx.x;
    if (i >= n) return;
    g_dinv[0][i] = rsqrtf((float)g_deg[0][i] + 1.0f);
    g_dinv[1][i] = rsqrtf((float)g_deg[1][i] + 1.0f);
}

// ---------------- 3-kernel exclusive scan of g_deg -> g_off ----------------
__global__ void k_scan1(int n) {
    int b = blockIdx.y;
    int tid = threadIdx.x;
    int i = blockIdx.x * 256 + tid;
    int v = (i < n) ? g_deg[b][i] : 0;
    __shared__ int s[256];
    s[tid] = v; __syncthreads();
    #pragma unroll
    for (int d = 1; d < 256; d <<= 1) {
        int t = (tid >= d) ? s[tid - d] : 0;
        __syncthreads();
        s[tid] += t;
        __syncthreads();
    }
    if (i < n) g_off[b][i] = s[tid] - v;       // exclusive within block
    if (tid == 255) g_bsum[b][blockIdx.x] = s[255];
}

__global__ void k_scan2(int nb) {
    int b = blockIdx.y;
    int tid = threadIdx.x;                     // 512 threads
    int v = (tid < nb) ? g_bsum[b][tid] : 0;
    __shared__ int s[512];
    s[tid] = v; __syncthreads();
    #pragma unroll
    for (int d = 1; d < 512; d <<= 1) {
        int t = (tid >= d) ? s[tid - d] : 0;
        __syncthreads();
        s[tid] += t;
        __syncthreads();
    }
    if (tid < nb) g_bpre[b][tid] = s[tid] - v; // exclusive block prefix
}

__global__ void k_scan3(int n) {
    int b = blockIdx.y;
    int i = blockIdx.x * 256 + threadIdx.x;
    if (i < n) g_off[b][i] += g_bpre[b][blockIdx.x];
}

__global__ void k_fill(const int* __restrict__ ei, const int* __restrict__ vei, int E) {
    int e = blockIdx.x * blockDim.x + threadIdx.x;
    if (e >= E) return;
    {
        int s = ei[e], d = ei[E + e];
        int p = g_off[0][d] + atomicAdd(&g_fill[0][d], 1);
        g_csr[0][p] = s;
    }
    {
        int s = vei[e], d = vei[E + e];
        int p = g_off[1][d] + atomicAdd(&g_fill[1][d], 1);
        g_csr[1][p] = s;
    }
}

// ---------------- x = embed[tok] + pe @ Wt + bt  (written to d_out) --------
__global__ void k_x(const int* __restrict__ tok, const float* __restrict__ pe,
                    const float* __restrict__ emb, const float* __restrict__ Wt,
                    const float* __restrict__ bt, float* __restrict__ xout, int n) {
    int idx = blockIdx.x * blockDim.x + threadIdx.x;
    if (idx >= n * HDIM) return;
    int node = idx >> 7;
    int h = idx & 127;
    int t = tok[node];
    const float* pn = pe + (size_t)node * 5;
    float acc = emb[t * HDIM + h] + bt[h];
    #pragma unroll
    for (int p = 0; p < 5; ++p) acc = fmaf(pn[p], Wt[p * HDIM + h], acc);
    xout[idx] = acc;
}

// ---------------- tf32 tensor-core GEMM (3xTF32 compensated) ---------------
// g_hx[N,256] = x[N,128] @ [W1 | Wv1].  Block: 128x128 tile (branch = blockIdx.y),
// 256 threads = 8 warps in 4(m) x 2(n), warp tile 32x64, BK = 16.
// Each operand element split into (hi, lo) tf32 at smem-staging time;
// D += a_hi*b_hi + a_lo*b_hi + a_hi*b_lo  (fp32-grade accuracy).

__device__ __forceinline__ uint2 tf32split(float f) {
    uint32_t hi;
    asm("cvt.rna.tf32.f32 %0, %1;" : "=r"(hi) : "f"(f));
    float lo = f - __uint_as_float(hi);
    uint32_t lou;
    asm("cvt.rna.tf32.f32 %0, %1;" : "=r"(lou) : "f"(lo));
    return make_uint2(hi, lou);
}

__device__ __forceinline__ void mma8(float* d, const uint32_t* a, const uint32_t* b) {
    asm volatile(
        "mma.sync.aligned.m16n8k8.row.col.f32.tf32.tf32.f32 "
        "{%0,%1,%2,%3}, {%4,%5,%6,%7}, {%8,%9}, {%0,%1,%2,%3};"
        : "+f"(d[0]), "+f"(d[1]), "+f"(d[2]), "+f"(d[3])
        : "r"(a[0]), "r"(a[1]), "r"(a[2]), "r"(a[3]), "r"(b[0]), "r"(b[1]));
}

__global__ __launch_bounds__(256)
void k_gemm(const float* __restrict__ A, const float* __restrict__ W1,
            const float* __restrict__ Wv1, int M) {
    const float* B = blockIdx.y ? Wv1 : W1;     // [128,128] row-major (K x N)
    int row0 = blockIdx.x * 128;

    __shared__ uint2 sA[128][17];               // (hi,lo) per element, [m][k]
    __shared__ uint2 sB[16][130];               // (hi,lo) per element, [k][n]

    int tid  = threadIdx.x;
    int warp = tid >> 5;
    int lane = tid & 31;
    int wm = warp & 3;                          // 0..3 -> m offset *32
    int wn = warp >> 2;                         // 0..1 -> n offset *64
    int grp = lane >> 2;                        // 0..7
    int tig = lane & 3;                         // 0..3

    float acc[2][8][4];
    #pragma unroll
    for (int mt = 0; mt < 2; ++mt)
        #pragma unroll
        for (int nt = 0; nt < 8; ++nt)
            #pragma unroll
            for (int i = 0; i < 4; ++i) acc[mt][nt][i] = 0.0f;

    for (int k0g = 0; k0g < 128; k0g += 16) {
        // --- stage A tile [128 x 16] and B tile [16 x 128], split hi/lo ---
        #pragma unroll
        for (int it = 0; it < 2; ++it) {
            int f = tid + it * 256;             // 0..511 float4 slots
            int ar = f >> 2;                    // 0..127
            int ac = (f & 3) * 4;               // 0,4,8,12
            int gr = row0 + ar;
            float4 av = make_float4(0.f, 0.f, 0.f, 0.f);
            if (gr < M) av = *(const float4*)(A + (size_t)gr * 128 + k0g + ac);
            sA[ar][ac + 0] = tf32split(av.x);
            sA[ar][ac + 1] = tf32split(av.y);
            sA[ar][ac + 2] = tf32split(av.z);
            sA[ar][ac + 3] = tf32split(av.w);

            int kr = f >> 5;                    // 0..15
            int bc = (f & 31) * 4;              // 0..124
            float4 bv = *(const float4*)(B + (k0g + kr) * 128 + bc);
            sB[kr][bc + 0] = tf32split(bv.x);
            sB[kr][bc + 1] = tf32split(bv.y);
            sB[kr][bc + 2] = tf32split(bv.z);
            sB[kr][bc + 3] = tf32split(bv.w);
        }
        __syncthreads();

        #pragma unroll
        for (int kk = 0; kk < 2; ++kk) {
            int kb = kk * 8;
            uint32_t ah[2][4], al[2][4];
            #pragma unroll
            for (int mt = 0; mt < 2; ++mt) {
                int r = wm * 32 + mt * 16 + grp;
                uint2 v0 = sA[r][kb + tig];
                uint2 v1 = sA[r + 8][kb + tig];
                uint2 v2 = sA[r][kb + tig + 4];
                uint2 v3 = sA[r + 8][kb + tig + 4];
                ah[mt][0] = v0.x; al[mt][0] = v0.y;
                ah[mt][1] = v1.x; al[mt][1] = v1.y;
                ah[mt][2] = v2.x; al[mt][2] = v2.y;
                ah[mt][3] = v3.x; al[mt][3] = v3.y;
            }
            #pragma unroll
            for (int nt = 0; nt < 8; ++nt) {
                int c = wn * 64 + nt * 8 + grp;
                uint2 w0 = sB[kb + tig][c];
                uint2 w1 = sB[kb + tig + 4][c];
                uint32_t bh[2] = { w0.x, w1.x };
                uint32_t bl[2] = { w0.y, w1.y };
                #pragma unroll
                for (int mt = 0; mt < 2; ++mt) {
                    mma8(acc[mt][nt], ah[mt], bh);
                    mma8(acc[mt][nt], al[mt], bh);
                    mma8(acc[mt][nt], ah[mt], bl);
                }
            }
        }
        __syncthreads();
    }

    // --- epilogue: D fragment (c0,c1)@row, (c2,c3)@row+8, cols tig*2, tig*2+1
    int colbase = blockIdx.y * 128 + wn * 64;
    #pragma unroll
    for (int mt = 0; mt < 2; ++mt) {
        int r0 = row0 + wm * 32 + mt * 16 + grp;
        #pragma unroll
        for (int nt = 0; nt < 8; ++nt) {
            int gc = colbase + nt * 8 + tig * 2;
            if (r0 < M)
                *(float2*)&g_hx[(size_t)r0 * 256 + gc] =
                    make_float2(acc[mt][nt][0], acc[mt][nt][1]);
            if (r0 + 8 < M)
                *(float2*)&g_hx[(size_t)(r0 + 8) * 256 + gc] =
                    make_float2(acc[mt][nt][2], acc[mt][nt][3]);
        }
    }
}

// -------- conv1 aggregation + bias + relu + layer-2 dot (fused) -> g_h2 ----
// One warp per (node, branch); 128 dims -> float4 per lane; dot with W2 and
// warp-reduce to a scalar (eliminates the g_h1 round-trip entirely).
__global__ void k_agg1(const float* __restrict__ b1, const float* __restrict__ bv1,
                       const float* __restrict__ W2, const float* __restrict__ Wv2, int n) {
    int warp = (blockIdx.x * blockDim.x + threadIdx.x) >> 5;
    int lane = threadIdx.x & 31;
    if (warp >= 2 * n) return;
    int br = (warp >= n) ? 1 : 0;
    int node = br ? (warp - n) : warp;
    int start = g_off[br][node];
    int cnt = g_deg[br][node];
    int half = br * 128;
    float4 acc = make_float4(0.f, 0.f, 0.f, 0.f);
    for (int e = 0; e < cnt; ++e) {
        int s = g_csr[br][start + e];
        float w = g_dinv[br][s];
        float4 v = *(const float4*)&g_hx[(size_t)s * 256 + half + lane * 4];
        acc.x = fmaf(v.x, w, acc.x);
        acc.y = fmaf(v.y, w, acc.y);
        acc.z = fmaf(v.z, w, acc.z);
        acc.w = fmaf(v.w, w, acc.w);
    }
    float di = g_dinv[br][node];
    float d2 = di * di;
    float4 sv = *(const float4*)&g_hx[(size_t)node * 256 + half + lane * 4];
    const float* bias = br ? bv1 : b1;
    float4 bb = *(const float4*)&bias[lane * 4];
    float4 r;
    r.x = fmaxf(fmaf(acc.x, di, fmaf(sv.x, d2, bb.x)), 0.f);
    r.y = fmaxf(fmaf(acc.y, di, fmaf(sv.y, d2, bb.y)), 0.f);
    r.z = fmaxf(fmaf(acc.z, di, fmaf(sv.z, d2, bb.z)), 0.f);
    r.w = fmaxf(fmaf(acc.w, di, fmaf(sv.w, d2, bb.w)), 0.f);

    const float* w2 = br ? Wv2 : W2;
    float4 ww = *(const float4*)&w2[lane * 4];
    float s = r.x * ww.x + r.y * ww.y + r.z * ww.z + r.w * ww.w;
    #pragma unroll
    for (int o = 16; o > 0; o >>= 1)
        s += __shfl_down_sync(0xFFFFFFFFu, s, o);
    if (lane == 0) g_h2[br][node] = s;
}

// -------- conv2 aggregation (scalar) + sum branches + graph pooling --------
__global__ void k_out(const int* __restrict__ batch, const float* __restrict__ b2,
                      const float* __restrict__ bv2, float* __restrict__ y, int n) {
    int node = blockIdx.x * blockDim.x + threadIdx.x;
    if (node >= n) return;
    float acc = b2[0] + bv2[0];
    #pragma unroll
    for (int br = 0; br < 2; ++br) {
        int start = g_off[br][node];
        int cnt = g_deg[br][node];
        float t = 0.f;
        for (int e = 0; e < cnt; ++e) {
            int s = g_csr[br][start + e];
            t = fmaf(g_h2[br][s], g_dinv[br][s], t);
        }
        float di = g_dinv[br][node];
        acc += di * t + g_h2[br][node] * di * di;
    }
    atomicAdd(&y[batch[node]], acc);
}

// ---------------------------------------------------------------------------
extern "C" void kernel_launch(void* const* d_in, const int* in_sizes, int n_in,
                              void* d_out, int out_size) {
    const int*   tok  = (const int*)  d_in[0];
    const float* pe   = (const float*)d_in[1];
    const int*   ei   = (const int*)  d_in[2];
    const int*   vei  = (const int*)  d_in[3];
    const int*   batch= (const int*)  d_in[4];
    const float* emb  = (const float*)d_in[5];
    const float* Wt   = (const float*)d_in[6];
    const float* bt   = (const float*)d_in[7];
    const float* W1   = (const float*)d_in[8];
    const float* b1   = (const float*)d_in[9];
    const float* W2   = (const float*)d_in[10];
    const float* b2   = (const float*)d_in[11];
    const float* Wv1  = (const float*)d_in[12];
    const float* bv1  = (const float*)d_in[13];
    const float* Wv2  = (const float*)d_in[14];
    const float* bv2  = (const float*)d_in[15];

    int N = in_sizes[0];              // 100000
    int E = in_sizes[2] / 2;          // 220000
    int G = out_size - N * HDIM;      // 4096 (output = [y | x])
    float* y = (float*)d_out;
    float* xout = y + G;

    int nz = (N > G) ? N : G;
    k_zero<<<(nz + 255) / 256, 256>>>(N, y, G);
    k_deg<<<(E + 255) / 256, 256>>>(ei, vei, E);
    k_dinv<<<(N + 255) / 256, 256>>>(N);

    int NB = (N + 255) / 256;
    k_scan1<<<dim3(NB, 2), 256>>>(N);
    k_scan2<<<dim3(1, 2), 512>>>(NB);
    k_scan3<<<dim3(NB, 2), 256>>>(N);
    k_fill<<<(E + 255) / 256, 256>>>(ei, vei, E);

    k_x<<<(N * HDIM + 255) / 256, 256>>>(tok, pe, emb, Wt, bt, xout, N);
    k_gemm<<<dim3((N + 127) / 128, 2), 256>>>(xout, W1, Wv1, N);
    k_agg1<<<(2 * N * 32 + 255) / 256, 256>>>(b1, bv1, W2, Wv2, N);
    k_out<<<(N + 255) / 256, 256>>>(batch, b2, bv2, y, N);
}

// round 12
// speedup vs baseline: 1.0941x; 1.0006x over previous
#include <cuda_runtime.h>
#include <math.h>
#include <stdint.h>

// Problem-shape capacities (actual sizes read from in_sizes at runtime).
#define HDIM   128
#define NMAX   100096
#define EMAX   221184
#define NBMAX  512     // max scan blocks: ceil(NMAX/256) = 392 <= 512

// ---------------- scratch (device globals; allocation is forbidden) --------
__device__ float g_hx[(size_t)NMAX * 256];   // x @ [W1 | Wv1]
__device__ float g_dinv[2][NMAX];
__device__ int   g_deg [2][NMAX];
__device__ int   g_off [2][NMAX];
__device__ int   g_fill[2][NMAX];
__device__ int   g_csr [2][EMAX];
__device__ float g_h2  [2][NMAX];
__device__ int   g_bsum[2][NBMAX];
__device__ int   g_bpre[2][NBMAX];

// ---------------- setup kernels --------------------------------------------
__global__ void k_zero(int n, float* y, int g) {
    int i = blockIdx.x * blockDim.x + threadIdx.x;
    if (i < n) {
        g_deg[0][i] = 0; g_deg[1][i] = 0;
        g_fill[0][i] = 0; g_fill[1][i] = 0;
    }
    if (i < g) y[i] = 0.0f;
}

__global__ void k_deg(const int* __restrict__ ei, const int* __restrict__ vei, int E) {
    int e = blockIdx.x * blockDim.x + threadIdx.x;
    if (e >= E) return;
    atomicAdd(&g_deg[0][ei [E + e]], 1);
    atomicAdd(&g_deg[1][vei[E + e]], 1);
}

__global__ void k_dinv(int n) {
    int i = blockIdx.x * blockDim.x + threadIdx.x;
    if (i >= n) return;
    g_dinv[0][i] = rsqrtf((float)g_deg[0][i] + 1.0f);
    g_dinv[1][i] = rsqrtf((float)g_deg[1][i] + 1.0f);
}

// ---------------- 3-kernel exclusive scan of g_deg -> g_off ----------------
__global__ void k_scan1(int n) {
    int b = blockIdx.y;
    int tid = threadIdx.x;
    int i = blockIdx.x * 256 + tid;
    int v = (i < n) ? g_deg[b][i] : 0;
    __shared__ int s[256];
    s[tid] = v; __syncthreads();
    #pragma unroll
    for (int d = 1; d < 256; d <<= 1) {
        int t = (tid >= d) ? s[tid - d] : 0;
        __syncthreads();
        s[tid] += t;
        __syncthreads();
    }
    if (i < n) g_off[b][i] = s[tid] - v;       // exclusive within block
    if (tid == 255) g_bsum[b][blockIdx.x] = s[255];
}

__global__ void k_scan2(int nb) {
    int b = blockIdx.y;
    int tid = threadIdx.x;                     // 512 threads
    int v = (tid < nb) ? g_bsum[b][tid] : 0;
    __shared__ int s[512];
    s[tid] = v; __syncthreads();
    #pragma unroll
    for (int d = 1; d < 512; d <<= 1) {
        int t = (tid >= d) ? s[tid - d] : 0;
        __syncthreads();
        s[tid] += t;
        __syncthreads();
    }
    if (tid < nb) g_bpre[b][tid] = s[tid] - v; // exclusive block prefix
}

__global__ void k_scan3(int n) {
    int b = blockIdx.y;
    int i = blockIdx.x * 256 + threadIdx.x;
    if (i < n) g_off[b][i] += g_bpre[b][blockIdx.x];
}

__global__ void k_fill(const int* __restrict__ ei, const int* __restrict__ vei, int E) {
    int e = blockIdx.x * blockDim.x + threadIdx.x;
    if (e >= E) return;
    {
        int s = ei[e], d = ei[E + e];
        int p = g_off[0][d] + atomicAdd(&g_fill[0][d], 1);
        g_csr[0][p] = s;
    }
    {
        int s = vei[e], d = vei[E + e];
        int p = g_off[1][d] + atomicAdd(&g_fill[1][d], 1);
        g_csr[1][p] = s;
    }
}

// ---------------- x = embed[tok] + pe @ Wt + bt  (written to d_out) --------
__global__ void k_x(const int* __restrict__ tok, const float* __restrict__ pe,
                    const float* __restrict__ emb, const float* __restrict__ Wt,
                    const float* __restrict__ bt, float* __restrict__ xout, int n) {
    int idx = blockIdx.x * blockDim.x + threadIdx.x;
    if (idx >= n * HDIM) return;
    int node = idx >> 7;
    int h = idx & 127;
    int t = tok[node];
    const float* pn = pe + (size_t)node * 5;
    float acc = emb[t * HDIM + h] + bt[h];
    #pragma unroll
    for (int p = 0; p < 5; ++p) acc = fmaf(pn[p], Wt[p * HDIM + h], acc);
    xout[idx] = acc;
}

// ---------------- tf32 tensor-core GEMM (3xTF32 compensated) ---------------
// g_hx[N,256] = x[N,128] @ [W1 | Wv1].  Block: 128x128 tile (branch = blockIdx.y),
// 256 threads = 8 warps in 4(m) x 2(n), warp tile 32x64, BK = 16.
// Each operand element split into (hi, lo) tf32 at smem-staging time;
// D += a_hi*b_hi + a_lo*b_hi + a_hi*b_lo  (fp32-grade accuracy).

__device__ __forceinline__ uint2 tf32split(float f) {
    uint32_t hi;
    asm("cvt.rna.tf32.f32 %0, %1;" : "=r"(hi) : "f"(f));
    float lo = f - __uint_as_float(hi);
    uint32_t lou;
    asm("cvt.rna.tf32.f32 %0, %1;" : "=r"(lou) : "f"(lo));
    return make_uint2(hi, lou);
}

__device__ __forceinline__ void mma8(float* d, const uint32_t* a, const uint32_t* b) {
    asm volatile(
        "mma.sync.aligned.m16n8k8.row.col.f32.tf32.tf32.f32 "
        "{%0,%1,%2,%3}, {%4,%5,%6,%7}, {%8,%9}, {%0,%1,%2,%3};"
        : "+f"(d[0]), "+f"(d[1]), "+f"(d[2]), "+f"(d[3])
        : "r"(a[0]), "r"(a[1]), "r"(a[2]), "r"(a[3]), "r"(b[0]), "r"(b[1]));
}

__global__ __launch_bounds__(256)
void k_gemm(const float* __restrict__ A, const float* __restrict__ W1,
            const float* __restrict__ Wv1, int M) {
    const float* B = blockIdx.y ? Wv1 : W1;     // [128,128] row-major (K x N)
    int row0 = blockIdx.x * 128;

    __shared__ uint2 sA[128][17];               // (hi,lo) per element, [m][k]
    __shared__ uint2 sB[16][130];               // (hi,lo) per element, [k][n]

    int tid  = threadIdx.x;
    int warp = tid >> 5;
    int lane = tid & 31;
    int wm = warp & 3;                          // 0..3 -> m offset *32
    int wn = warp >> 2;                         // 0..1 -> n offset *64
    int grp = lane >> 2;                        // 0..7
    int tig = lane & 3;                         // 0..3

    float acc[2][8][4];
    #pragma unroll
    for (int mt = 0; mt < 2; ++mt)
        #pragma unroll
        for (int nt = 0; nt < 8; ++nt)
            #pragma unroll
            for (int i = 0; i < 4; ++i) acc[mt][nt][i] = 0.0f;

    for (int k0g = 0; k0g < 128; k0g += 16) {
        // --- stage A tile [128 x 16] and B tile [16 x 128], split hi/lo ---
        #pragma unroll
        for (int it = 0; it < 2; ++it) {
            int f = tid + it * 256;             // 0..511 float4 slots
            int ar = f >> 2;                    // 0..127
            int ac = (f & 3) * 4;               // 0,4,8,12
            int gr = row0 + ar;
            float4 av = make_float4(0.f, 0.f, 0.f, 0.f);
            if (gr < M) av = *(const float4*)(A + (size_t)gr * 128 + k0g + ac);
            sA[ar][ac + 0] = tf32split(av.x);
            sA[ar][ac + 1] = tf32split(av.y);
            sA[ar][ac + 2] = tf32split(av.z);
            sA[ar][ac + 3] = tf32split(av.w);

            int kr = f >> 5;                    // 0..15
            int bc = (f & 31) * 4;              // 0..124
            float4 bv = *(const float4*)(B + (k0g + kr) * 128 + bc);
            sB[kr][bc + 0] = tf32split(bv.x);
            sB[kr][bc + 1] = tf32split(bv.y);
            sB[kr][bc + 2] = tf32split(bv.z);
            sB[kr][bc + 3] = tf32split(bv.w);
        }
        __syncthreads();

        #pragma unroll
        for (int kk = 0; kk < 2; ++kk) {
            int kb = kk * 8;
            uint32_t ah[2][4], al[2][4];
            #pragma unroll
            for (int mt = 0; mt < 2; ++mt) {
                int r = wm * 32 + mt * 16 + grp;
                uint2 v0 = sA[r][kb + tig];
                uint2 v1 = sA[r + 8][kb + tig];
                uint2 v2 = sA[r][kb + tig + 4];
                uint2 v3 = sA[r + 8][kb + tig + 4];
                ah[mt][0] = v0.x; al[mt][0] = v0.y;
                ah[mt][1] = v1.x; al[mt][1] = v1.y;
                ah[mt][2] = v2.x; al[mt][2] = v2.y;
                ah[mt][3] = v3.x; al[mt][3] = v3.y;
            }
            #pragma unroll
            for (int nt = 0; nt < 8; ++nt) {
                int c = wn * 64 + nt * 8 + grp;
                uint2 w0 = sB[kb + tig][c];
                uint2 w1 = sB[kb + tig + 4][c];
                uint32_t bh[2] = { w0.x, w1.x };
                uint32_t bl[2] = { w0.y, w1.y };
                #pragma unroll
                for (int mt = 0; mt < 2; ++mt) {
                    mma8(acc[mt][nt], ah[mt], bh);
                    mma8(acc[mt][nt], al[mt], bh);
                    mma8(acc[mt][nt], ah[mt], bl);
                }
            }
        }
        __syncthreads();
    }

    // --- epilogue: D fragment (c0,c1)@row, (c2,c3)@row+8, cols tig*2, tig*2+1
    int colbase = blockIdx.y * 128 + wn * 64;
    #pragma unroll
    for (int mt = 0; mt < 2; ++mt) {
        int r0 = row0 + wm * 32 + mt * 16 + grp;
        #pragma unroll
        for (int nt = 0; nt < 8; ++nt) {
            int gc = colbase + nt * 8 + tig * 2;
            if (r0 < M)
                *(float2*)&g_hx[(size_t)r0 * 256 + gc] =
                    make_float2(acc[mt][nt][0], acc[mt][nt][1]);
            if (r0 + 8 < M)
                *(float2*)&g_hx[(size_t)(r0 + 8) * 256 + gc] =
                    make_float2(acc[mt][nt][2], acc[mt][nt][3]);
        }
    }
}

// -------- conv1 aggregation + bias + relu + layer-2 dot (fused) -> g_h2 ----
// One warp per (node, branch); 128 dims -> float4 per lane; dot with W2 and
// warp-reduce to a scalar (eliminates the g_h1 round-trip entirely).
__global__ void k_agg1(const float* __restrict__ b1, const float* __restrict__ bv1,
                       const float* __restrict__ W2, const float* __restrict__ Wv2, int n) {
    int warp = (blockIdx.x * blockDim.x + threadIdx.x) >> 5;
    int lane = threadIdx.x & 31;
    if (warp >= 2 * n) return;
    int br = (warp >= n) ? 1 : 0;
    int node = br ? (warp - n) : warp;
    int start = g_off[br][node];
    int cnt = g_deg[br][node];
    int half = br * 128;
    float4 acc = make_float4(0.f, 0.f, 0.f, 0.f);
    for (int e = 0; e < cnt; ++e) {
        int s = g_csr[br][start + e];
        float w = g_dinv[br][s];
        float4 v = *(const float4*)&g_hx[(size_t)s * 256 + half + lane * 4];
        acc.x = fmaf(v.x, w, acc.x);
        acc.y = fmaf(v.y, w, acc.y);
        acc.z = fmaf(v.z, w, acc.z);
        acc.w = fmaf(v.w, w, acc.w);
    }
    float di = g_dinv[br][node];
    float d2 = di * di;
    float4 sv = *(const float4*)&g_hx[(size_t)node * 256 + half + lane * 4];
    const float* bias = br ? bv1 : b1;
    float4 bb = *(const float4*)&bias[lane * 4];
    float4 r;
    r.x = fmaxf(fmaf(acc.x, di, fmaf(sv.x, d2, bb.x)), 0.f);
    r.y = fmaxf(fmaf(acc.y, di, fmaf(sv.y, d2, bb.y)), 0.f);
    r.z = fmaxf(fmaf(acc.z, di, fmaf(sv.z, d2, bb.z)), 0.f);
    r.w = fmaxf(fmaf(acc.w, di, fmaf(sv.w, d2, bb.w)), 0.f);

    const float* w2 = br ? Wv2 : W2;
    float4 ww = *(const float4*)&w2[lane * 4];
    float s = r.x * ww.x + r.y * ww.y + r.z * ww.z + r.w * ww.w;
    #pragma unroll
    for (int o = 16; o > 0; o >>= 1)
        s += __shfl_down_sync(0xFFFFFFFFu, s, o);
    if (lane == 0) g_h2[br][node] = s;
}

// -------- conv2 aggregation (scalar) + sum branches + graph pooling --------
__global__ void k_out(const int* __restrict__ batch, const float* __restrict__ b2,
                      const float* __restrict__ bv2, float* __restrict__ y, int n) {
    int node = blockIdx.x * blockDim.x + threadIdx.x;
    if (node >= n) return;
    float acc = b2[0] + bv2[0];
    #pragma unroll
    for (int br = 0; br < 2; ++br) {
        int start = g_off[br][node];
        int cnt = g_deg[br][node];
        float t = 0.f;
        for (int e = 0; e < cnt; ++e) {
            int s = g_csr[br][start + e];
            t = fmaf(g_h2[br][s], g_dinv[br][s], t);
        }
        float di = g_dinv[br][node];
        acc += di * t + g_h2[br][node] * di * di;
    }
    atomicAdd(&y[batch[node]], acc);
}

// ---------------------------------------------------------------------------
extern "C" void kernel_launch(void* const* d_in, const int* in_sizes, int n_in,
                              void* d_out, int out_size) {
    const int*   tok  = (const int*)  d_in[0];
    const float* pe   = (const float*)d_in[1];
    const int*   ei   = (const int*)  d_in[2];
    const int*   vei  = (const int*)  d_in[3];
    const int*   batch= (const int*)  d_in[4];
    const float* emb  = (const float*)d_in[5];
    const float* Wt   = (const float*)d_in[6];
    const float* bt   = (const float*)d_in[7];
    const float* W1   = (const float*)d_in[8];
    const float* b1   = (const float*)d_in[9];
    const float* W2   = (const float*)d_in[10];
    const float* b2   = (const float*)d_in[11];
    const float* Wv1  = (const float*)d_in[12];
    const float* bv1  = (const float*)d_in[13];
    const float* Wv2  = (const float*)d_in[14];
    const float* bv2  = (const float*)d_in[15];

    int N = in_sizes[0];              // 100000
    int E = in_sizes[2] / 2;          // 220000
    int G = out_size - N * HDIM;      // 4096 (output = [y | x])
    float* y = (float*)d_out;
    float* xout = y + G;

    int nz = (N > G) ? N : G;
    k_zero<<<(nz + 255) / 256, 256>>>(N, y, G);
    k_deg<<<(E + 255) / 256, 256>>>(ei, vei, E);
    k_dinv<<<(N + 255) / 256, 256>>>(N);

    int NB = (N + 255) / 256;
    k_scan1<<<dim3(NB, 2), 256>>>(N);
    k_scan2<<<dim3(1, 2), 512>>>(NB);
    k_scan3<<<dim3(NB, 2), 256>>>(N);
    k_fill<<<(E + 255) / 256, 256>>>(ei, vei, E);

    k_x<<<(N * HDIM + 255) / 256, 256>>>(tok, pe, emb, Wt, bt, xout, N);
    k_gemm<<<dim3((N + 127) / 128, 2), 256>>>(xout, W1, Wv1, N);
    k_agg1<<<(2 * N * 32 + 255) / 256, 256>>>(b1, bv1, W2, Wv2, N);
    k_out<<<(N + 255) / 256, 256>>>(batch, b2, bv2, y, N);
}

// round 13
// speedup vs baseline: 1.0954x; 1.0011x over previous
#include <cuda_runtime.h>
#include <math.h>
#include <stdint.h>

// Problem-shape capacities (actual sizes read from in_sizes at runtime).
#define HDIM   128
#define NMAX   100096
#define EMAX   221184
#define NBMAX  512     // max scan blocks: ceil(NMAX/256) = 392 <= 512

// ---------------- scratch (device globals; allocation is forbidden) --------
__device__ float g_hx[(size_t)NMAX * 256];   // x @ [W1 | Wv1]
__device__ float g_dinv[2][NMAX];
__device__ int   g_deg [2][NMAX];
__device__ int   g_off [2][NMAX];
__device__ int   g_fill[2][NMAX];
__device__ int   g_csr [2][EMAX];
__device__ float g_h2  [2][NMAX];
__device__ int   g_bsum[2][NBMAX];
__device__ int   g_bpre[2][NBMAX];

// ---------------- setup kernels --------------------------------------------
__global__ void k_zero(int n, float* y, int g) {
    int i = blockIdx.x * blockDim.x + threadIdx.x;
    if (i < n) {
        g_deg[0][i] = 0; g_deg[1][i] = 0;
        g_fill[0][i] = 0; g_fill[1][i] = 0;
    }
    if (i < g) y[i] = 0.0f;
}

__global__ void k_deg(const int* __restrict__ ei, const int* __restrict__ vei, int E) {
    int e = blockIdx.x * blockDim.x + threadIdx.x;
    if (e >= E) return;
    atomicAdd(&g_deg[0][ei [E + e]], 1);
    atomicAdd(&g_deg[1][vei[E + e]], 1);
}

__global__ void k_dinv(int n) {
    int i = blockIdx.x * blockDim.x + threadIdx.x;
    if (i >= n) return;
    g_dinv[0][i] = rsqrtf((float)g_deg[0][i] + 1.0f);
    g_dinv[1][i] = rsqrtf((float)g_deg[1][i] + 1.0f);
}

// ---------------- 3-kernel exclusive scan of g_deg -> g_off ----------------
__global__ void k_scan1(int n) {
    int b = blockIdx.y;
    int tid = threadIdx.x;
    int i = blockIdx.x * 256 + tid;
    int v = (i < n) ? g_deg[b][i] : 0;
    __shared__ int s[256];
    s[tid] = v; __syncthreads();
    #pragma unroll
    for (int d = 1; d < 256; d <<= 1) {
        int t = (tid >= d) ? s[tid - d] : 0;
        __syncthreads();
        s[tid] += t;
        __syncthreads();
    }
    if (i < n) g_off[b][i] = s[tid] - v;       // exclusive within block
    if (tid == 255) g_bsum[b][blockIdx.x] = s[255];
}

__global__ void k_scan2(int nb) {
    int b = blockIdx.y;
    int tid = threadIdx.x;                     // 512 threads
    int v = (tid < nb) ? g_bsum[b][tid] : 0;
    __shared__ int s[512];
    s[tid] = v; __syncthreads();
    #pragma unroll
    for (int d = 1; d < 512; d <<= 1) {
        int t = (tid >= d) ? s[tid - d] : 0;
        __syncthreads();
        s[tid] += t;
        __syncthreads();
    }
    if (tid < nb) g_bpre[b][tid] = s[tid] - v; // exclusive block prefix
}

__global__ void k_scan3(int n) {
    int b = blockIdx.y;
    int i = blockIdx.x * 256 + threadIdx.x;
    if (i < n) g_off[b][i] += g_bpre[b][blockIdx.x];
}

__global__ void k_fill(const int* __restrict__ ei, const int* __restrict__ vei, int E) {
    int e = blockIdx.x * blockDim.x + threadIdx.x;
    if (e >= E) return;
    {
        int s = ei[e], d = ei[E + e];
        int p = g_off[0][d] + atomicAdd(&g_fill[0][d], 1);
        g_csr[0][p] = s;
    }
    {
        int s = vei[e], d = vei[E + e];
        int p = g_off[1][d] + atomicAdd(&g_fill[1][d], 1);
        g_csr[1][p] = s;
    }
}

// ---------------- x = embed[tok] + pe @ Wt + bt  (written to d_out) --------
__global__ void k_x(const int* __restrict__ tok, const float* __restrict__ pe,
                    const float* __restrict__ emb, const float* __restrict__ Wt,
                    const float* __restrict__ bt, float* __restrict__ xout, int n) {
    int idx = blockIdx.x * blockDim.x + threadIdx.x;
    if (idx >= n * HDIM) return;
    int node = idx >> 7;
    int h = idx & 127;
    int t = tok[node];
    const float* pn = pe + (size_t)node * 5;
    float acc = emb[t * HDIM + h] + bt[h];
    #pragma unroll
    for (int p = 0; p < 5; ++p) acc = fmaf(pn[p], Wt[p * HDIM + h], acc);
    xout[idx] = acc;
}

// ---------------- tf32 tensor-core GEMM (3xTF32 compensated) ---------------
// g_hx[N,256] = x[N,128] @ [W1 | Wv1].  Block: 128x128 tile (branch = blockIdx.y),
// 256 threads = 8 warps in 4(m) x 2(n), warp tile 32x64, BK = 16.
// Each operand element split into (hi, lo) tf32 at smem-staging time;
// D += a_hi*b_hi + a_lo*b_hi + a_hi*b_lo  (fp32-grade accuracy).

__device__ __forceinline__ uint2 tf32split(float f) {
    uint32_t hi;
    asm("cvt.rna.tf32.f32 %0, %1;" : "=r"(hi) : "f"(f));
    float lo = f - __uint_as_float(hi);
    uint32_t lou;
    asm("cvt.rna.tf32.f32 %0, %1;" : "=r"(lou) : "f"(lo));
    return make_uint2(hi, lou);
}

__device__ __forceinline__ void mma8(float* d, const uint32_t* a, const uint32_t* b) {
    asm volatile(
        "mma.sync.aligned.m16n8k8.row.col.f32.tf32.tf32.f32 "
        "{%0,%1,%2,%3}, {%4,%5,%6,%7}, {%8,%9}, {%0,%1,%2,%3};"
        : "+f"(d[0]), "+f"(d[1]), "+f"(d[2]), "+f"(d[3])
        : "r"(a[0]), "r"(a[1]), "r"(a[2]), "r"(a[3]), "r"(b[0]), "r"(b[1]));
}

__global__ __launch_bounds__(256)
void k_gemm(const float* __restrict__ A, const float* __restrict__ W1,
            const float* __restrict__ Wv1, int M) {
    const float* B = blockIdx.y ? Wv1 : W1;     // [128,128] row-major (K x N)
    int row0 = blockIdx.x * 128;

    __shared__ uint2 sA[128][17];               // (hi,lo) per element, [m][k]
    __shared__ uint2 sB[16][130];               // (hi,lo) per element, [k][n]

    int tid  = threadIdx.x;
    int warp = tid >> 5;
    int lane = tid & 31;
    int wm = warp & 3;                          // 0..3 -> m offset *32
    int wn = warp >> 2;                         // 0..1 -> n offset *64
    int grp = lane >> 2;                        // 0..7
    int tig = lane & 3;                         // 0..3

    float acc[2][8][4];
    #pragma unroll
    for (int mt = 0; mt < 2; ++mt)
        #pragma unroll
        for (int nt = 0; nt < 8; ++nt)
            #pragma unroll
            for (int i = 0; i < 4; ++i) acc[mt][nt][i] = 0.0f;

    for (int k0g = 0; k0g < 128; k0g += 16) {
        // --- stage A tile [128 x 16] and B tile [16 x 128], split hi/lo ---
        #pragma unroll
        for (int it = 0; it < 2; ++it) {
            int f = tid + it * 256;             // 0..511 float4 slots
            int ar = f >> 2;                    // 0..127
            int ac = (f & 3) * 4;               // 0,4,8,12
            int gr = row0 + ar;
            float4 av = make_float4(0.f, 0.f, 0.f, 0.f);
            if (gr < M) av = *(const float4*)(A + (size_t)gr * 128 + k0g + ac);
            sA[ar][ac + 0] = tf32split(av.x);
            sA[ar][ac + 1] = tf32split(av.y);
            sA[ar][ac + 2] = tf32split(av.z);
            sA[ar][ac + 3] = tf32split(av.w);

            int kr = f >> 5;                    // 0..15
            int bc = (f & 31) * 4;              // 0..124
            float4 bv = *(const float4*)(B + (k0g + kr) * 128 + bc);
            sB[kr][bc + 0] = tf32split(bv.x);
            sB[kr][bc + 1] = tf32split(bv.y);
            sB[kr][bc + 2] = tf32split(bv.z);
            sB[kr][bc + 3] = tf32split(bv.w);
        }
        __syncthreads();

        #pragma unroll
        for (int kk = 0; kk < 2; ++kk) {
            int kb = kk * 8;
            uint32_t ah[2][4], al[2][4];
            #pragma unroll
            for (int mt = 0; mt < 2; ++mt) {
                int r = wm * 32 + mt * 16 + grp;
                uint2 v0 = sA[r][kb + tig];
                uint2 v1 = sA[r + 8][kb + tig];
                uint2 v2 = sA[r][kb + tig + 4];
                uint2 v3 = sA[r + 8][kb + tig + 4];
                ah[mt][0] = v0.x; al[mt][0] = v0.y;
                ah[mt][1] = v1.x; al[mt][1] = v1.y;
                ah[mt][2] = v2.x; al[mt][2] = v2.y;
                ah[mt][3] = v3.x; al[mt][3] = v3.y;
            }
            #pragma unroll
            for (int nt = 0; nt < 8; ++nt) {
                int c = wn * 64 + nt * 8 + grp;
                uint2 w0 = sB[kb + tig][c];
                uint2 w1 = sB[kb + tig + 4][c];
                uint32_t bh[2] = { w0.x, w1.x };
                uint32_t bl[2] = { w0.y, w1.y };
                #pragma unroll
                for (int mt = 0; mt < 2; ++mt) {
                    mma8(acc[mt][nt], ah[mt], bh);
                    mma8(acc[mt][nt], al[mt], bh);
                    mma8(acc[mt][nt], ah[mt], bl);
                }
            }
        }
        __syncthreads();
    }

    // --- epilogue: D fragment (c0,c1)@row, (c2,c3)@row+8, cols tig*2, tig*2+1
    int colbase = blockIdx.y * 128 + wn * 64;
    #pragma unroll
    for (int mt = 0; mt < 2; ++mt) {
        int r0 = row0 + wm * 32 + mt * 16 + grp;
        #pragma unroll
        for (int nt = 0; nt < 8; ++nt) {
            int gc = colbase + nt * 8 + tig * 2;
            if (r0 < M)
                *(float2*)&g_hx[(size_t)r0 * 256 + gc] =
                    make_float2(acc[mt][nt][0], acc[mt][nt][1]);
            if (r0 + 8 < M)
                *(float2*)&g_hx[(size_t)(r0 + 8) * 256 + gc] =
                    make_float2(acc[mt][nt][2], acc[mt][nt][3]);
        }
    }
}

// -------- conv1 aggregation + bias + relu + layer-2 dot (fused) -> g_h2 ----
// One warp per (node, branch); 128 dims -> float4 per lane; dot with W2 and
// warp-reduce to a scalar (eliminates the g_h1 round-trip entirely).
__global__ void k_agg1(const float* __restrict__ b1, const float* __restrict__ bv1,
                       const float* __restrict__ W2, const float* __restrict__ Wv2, int n) {
    int warp = (blockIdx.x * blockDim.x + threadIdx.x) >> 5;
    int lane = threadIdx.x & 31;
    if (warp >= 2 * n) return;
    int br = (warp >= n) ? 1 : 0;
    int node = br ? (warp - n) : warp;
    int start = g_off[br][node];
    int cnt = g_deg[br][node];
    int half = br * 128;
    float4 acc = make_float4(0.f, 0.f, 0.f, 0.f);
    for (int e = 0; e < cnt; ++e) {
        int s = g_csr[br][start + e];
        float w = g_dinv[br][s];
        float4 v = *(const float4*)&g_hx[(size_t)s * 256 + half + lane * 4];
        acc.x = fmaf(v.x, w, acc.x);
        acc.y = fmaf(v.y, w, acc.y);
        acc.z = fmaf(v.z, w, acc.z);
        acc.w = fmaf(v.w, w, acc.w);
    }
    float di = g_dinv[br][node];
    float d2 = di * di;
    float4 sv = *(const float4*)&g_hx[(size_t)node * 256 + half + lane * 4];
    const float* bias = br ? bv1 : b1;
    float4 bb = *(const float4*)&bias[lane * 4];
    float4 r;
    r.x = fmaxf(fmaf(acc.x, di, fmaf(sv.x, d2, bb.x)), 0.f);
    r.y = fmaxf(fmaf(acc.y, di, fmaf(sv.y, d2, bb.y)), 0.f);
    r.z = fmaxf(fmaf(acc.z, di, fmaf(sv.z, d2, bb.z)), 0.f);
    r.w = fmaxf(fmaf(acc.w, di, fmaf(sv.w, d2, bb.w)), 0.f);

    const float* w2 = br ? Wv2 : W2;
    float4 ww = *(const float4*)&w2[lane * 4];
    float s = r.x * ww.x + r.y * ww.y + r.z * ww.z + r.w * ww.w;
    #pragma unroll
    for (int o = 16; o > 0; o >>= 1)
        s += __shfl_down_sync(0xFFFFFFFFu, s, o);
    if (lane == 0) g_h2[br][node] = s;
}

// -------- conv2 aggregation (scalar) + sum branches + graph pooling --------
__global__ void k_out(const int* __restrict__ batch, const float* __restrict__ b2,
                      const float* __restrict__ bv2, float* __restrict__ y, int n) {
    int node = blockIdx.x * blockDim.x + threadIdx.x;
    if (node >= n) return;
    float acc = b2[0] + bv2[0];
    #pragma unroll
    for (int br = 0; br < 2; ++br) {
        int start = g_off[br][node];
        int cnt = g_deg[br][node];
        float t = 0.f;
        for (int e = 0; e < cnt; ++e) {
            int s = g_csr[br][start + e];
            t = fmaf(g_h2[br][s], g_dinv[br][s], t);
        }
        float di = g_dinv[br][node];
        acc += di * t + g_h2[br][node] * di * di;
    }
    atomicAdd(&y[batch[node]], acc);
}

// ---------------------------------------------------------------------------
extern "C" void kernel_launch(void* const* d_in, const int* in_sizes, int n_in,
                              void* d_out, int out_size) {
    const int*   tok  = (const int*)  d_in[0];
    const float* pe   = (const float*)d_in[1];
    const int*   ei   = (const int*)  d_in[2];
    const int*   vei  = (const int*)  d_in[3];
    const int*   batch= (const int*)  d_in[4];
    const float* emb  = (const float*)d_in[5];
    const float* Wt   = (const float*)d_in[6];
    const float* bt   = (const float*)d_in[7];
    const float* W1   = (const float*)d_in[8];
    const float* b1   = (const float*)d_in[9];
    const float* W2   = (const float*)d_in[10];
    const float* b2   = (const float*)d_in[11];
    const float* Wv1  = (const float*)d_in[12];
    const float* bv1  = (const float*)d_in[13];
    const float* Wv2  = (const float*)d_in[14];
    const float* bv2  = (const float*)d_in[15];

    int N = in_sizes[0];              // 100000
    int E = in_sizes[2] / 2;          // 220000
    int G = out_size - N * HDIM;      // 4096 (output = [y | x])
    float* y = (float*)d_out;
    float* xout = y + G;

    int nz = (N > G) ? N : G;
    k_zero<<<(nz + 255) / 256, 256>>>(N, y, G);
    k_deg<<<(E + 255) / 256, 256>>>(ei, vei, E);
    k_dinv<<<(N + 255) / 256, 256>>>(N);

    int NB = (N + 255) / 256;
    k_scan1<<<dim3(NB, 2), 256>>>(N);
    k_scan2<<<dim3(1, 2), 512>>>(NB);
    k_scan3<<<dim3(NB, 2), 256>>>(N);
    k_fill<<<(E + 255) / 256, 256>>>(ei, vei, E);

    k_x<<<(N * HDIM + 255) / 256, 256>>>(tok, pe, emb, Wt, bt, xout, N);
    k_gemm<<<dim3((N + 127) / 128, 2), 256>>>(xout, W1, Wv1, N);
    k_agg1<<<(2 * N * 32 + 255) / 256, 256>>>(b1, bv1, W2, Wv2, N);
    k_out<<<(N + 255) / 256, 256>>>(batch, b2, bv2, y, N);
}